// round 14
// baseline (speedup 1.0000x reference)
#include <cuda_runtime.h>
#include <cuda_bf16.h>
#include <cuda_fp16.h>
#include <cstdint>

#define NA   100000
#define MM   12
#define AFD  64
#define NFD  41
#define KD   169
#define CD   128
#define NCONV 3
#define NCRY 100
#define APC  1000
#define HF   128
#define HID  64
#define EPSV 1e-5f

#define NBLK   148
#define TATOMS 5
#define NTILES (NA / TATOMS)   // 20000
#define TROWS  60
#define TSTRD  (NBLK * 2)      // 296 tile stride (2 groups per block)
#define KSTEPS 7               // K_rest = 112
#define ASTRE  120
#define ASTRB  240
#define NFP    48

#define G2BLK  1184

// ---- convg SMEM byte offsets (from 1024-aligned base) ----
#define WHI_OFF   0u
#define WLO_OFF   30720u
#define GA_OFF    61440u       // 4 stages (g*2+sb) x STG_B
#define STG_B     32128u       // Ahi 15360 | Alo 15360 | self 1360 | pad
#define SELF_IN   30720u
#define SIDX_OFF  189952u      // 4 x 64 i32
#define SMEM_USED 190976u
#define SMEM_DYN  (SMEM_USED + 1024u)
// stat-reduction overlay (after full __syncthreads)
#define SREDS_OFF GA_OFF
#define SREDQ_OFF (GA_OFF + 16896u)

// ---- selfg SMEM ----
#define SGA_HI  0u
#define SGA_LO  18432u
#define SGW_HI  36864u
#define SGW_LO  55296u
#define SGBIAS  73728u
#define SG_USED 74240u
#define SG_DYN  (SG_USED + 1024u)

typedef unsigned long long ull;

// ---------------- scratch (device globals) ----------------------------------
__device__ float g_fea0[NA * AFD];
__device__ float g_fea1[NA * AFD];
__device__ float g_summed[NA * AFD];
__device__ __half g_gated[NA * MM * CD];         // 307 MB fp16
__device__ __half g_self[NA * CD];               // 25.6 MB fp16
__device__ __nv_bfloat16 g_AH[NA * AFD], g_AL[NA * AFD];
__device__ __nv_bfloat16 g_NH[NA * MM * NFP], g_NL[NA * MM * NFP];
__device__ float g_part1[NBLK * 2 * CD];
__device__ float g_part2[G2BLK * 2 * AFD];
__device__ float g_sc1[CD], g_sh1[CD];
__device__ float g_sc2[AFD], g_sh2[AFD];

// ---------------- helpers ----------------------------------------------------
__device__ __forceinline__ uint32_t smem_u32(const void* p) {
    uint32_t a;
    asm("{ .reg .u64 t; cvta.to.shared.u64 t, %1; cvt.u32.u64 %0, t; }"
        : "=r"(a) : "l"(p));
    return a;
}

#define LDSM4(r, addr) \
    asm volatile("ldmatrix.sync.aligned.m8n8.x4.shared.b16 {%0,%1,%2,%3},[%4];" \
        : "=r"((r)[0]), "=r"((r)[1]), "=r"((r)[2]), "=r"((r)[3]) : "r"(addr))

#define MMA16(c, a, b) \
    asm volatile("mma.sync.aligned.m16n8k16.row.col.f32.bf16.bf16.f32 " \
        "{%0,%1,%2,%3},{%4,%5,%6,%7},{%8,%9},{%0,%1,%2,%3};" \
        : "+f"((c)[0]), "+f"((c)[1]), "+f"((c)[2]), "+f"((c)[3]) \
        : "r"((a)[0]), "r"((a)[1]), "r"((a)[2]), "r"((a)[3]), \
          "r"((b)[0]), "r"((b)[1]))

#define CPA16(dst, src) \
    asm volatile("cp.async.cg.shared.global [%0],[%1],16;" \
        :: "r"(dst), "l"(src) : "memory")
#define CPA_COMMIT() asm volatile("cp.async.commit_group;" ::: "memory")
#define CPA_WAIT1()  asm volatile("cp.async.wait_group 1;" ::: "memory")
#define GBAR(g) asm volatile("bar.sync %0, 256;" :: "r"((g) + 1) : "memory")

__device__ __forceinline__ void splitbf(float v, __nv_bfloat16& h, __nv_bfloat16& l) {
    h = __float2bfloat16(v);
    l = __float2bfloat16(v - __bfloat162float(h));
}
__device__ __forceinline__ float sigm(float x) {
    return __fdividef(1.0f, 1.0f + __expf(-x));
}
__device__ __forceinline__ float sftp(float x) {
    return fmaxf(x, 0.0f) + __logf(1.0f + __expf(-fabsf(x)));
}

// ---------------- embedding + bond preconversion -----------------------------
__global__ void embed2_k(const int* __restrict__ an, const float* __restrict__ emb) {
    int i = blockIdx.x * blockDim.x + threadIdx.x;
    if (i < NA * AFD) {
        int n = i >> 6, c = i & 63;
        float v = emb[an[n] * AFD + c];
        g_fea0[i] = v;
        splitbf(v, g_AH[i], g_AL[i]);
    }
}
__global__ void nbrcvt_k(const float* __restrict__ nbrf) {
    int i = blockIdx.x * blockDim.x + threadIdx.x;
    if (i < NA * MM * NFP) {
        int r = i / NFP, k = i - r * NFP;
        float v = (k < NFD) ? nbrf[r * NFD + k] : 0.0f;
        splitbf(v, g_NH[i], g_NL[i]);
    }
}

// ---------------- selfg: S = atom_fea @ W[0:64] + bias -> fp16 ---------------
__global__ void __launch_bounds__(512, 1) selfg_k(
    const float* __restrict__ Wl, const float* __restrict__ bl)
{
    extern __shared__ char smraw[];
    char* base = (char*)((((uintptr_t)smraw) + 1023) & ~(uintptr_t)1023);
    const uint32_t bu = smem_u32(base);

    const int tid = threadIdx.x, wid = tid >> 5, lane = tid & 31;
    const int warp_m = wid & 3, warp_n = wid >> 2;
    const int R0 = warp_m * 32, N0 = warp_n * 32;
    const int n0 = blockIdx.x * 128;

    for (int i = tid; i < (int)(SG_USED / 4); i += 512) ((uint32_t*)base)[i] = 0;
    __syncthreads();

    for (int i = tid; i < 128 * 8; i += 512) {
        int r = i >> 3, c = i & 7;
        uint4 vh = make_uint4(0, 0, 0, 0), vl = make_uint4(0, 0, 0, 0);
        if (n0 + r < NA) {
            vh = *(const uint4*)((const char*)g_AH + (size_t)(n0 + r) * 128 + c * 16);
            vl = *(const uint4*)((const char*)g_AL + (size_t)(n0 + r) * 128 + c * 16);
        }
        *(uint4*)(base + SGA_HI + r * 144 + c * 16) = vh;
        *(uint4*)(base + SGA_LO + r * 144 + c * 16) = vl;
    }
    for (int i = tid; i < 64 * 128; i += 512) {
        int k = i >> 7, c = i & 127;
        __nv_bfloat16 h, l;
        splitbf(Wl[k * CD + c], h, l);
        *(__nv_bfloat16*)(base + SGW_HI + c * 144 + k * 2) = h;
        *(__nv_bfloat16*)(base + SGW_LO + c * 144 + k * 2) = l;
    }
    if (tid < 128) ((float*)(base + SGBIAS))[tid] = bl[tid];
    __syncthreads();

    const uint32_t aoffb = (uint32_t)(((R0 + (lane & 15)) * 72 + (lane >> 4) * 8) * 2);
    const uint32_t aH0 = bu + SGA_HI + aoffb, aH1 = aH0 + 16 * 144;
    const uint32_t aL0 = bu + SGA_LO + aoffb, aL1 = aL0 + 16 * 144;
    const uint32_t boffb = (uint32_t)(((N0 + (lane & 7) + (lane >> 4) * 8) * 72
                                      + ((lane >> 3) & 1) * 8) * 2);
    const uint32_t bH0 = bu + SGW_HI + boffb, bH1 = bH0 + 16 * 144;
    const uint32_t bL0 = bu + SGW_LO + boffb, bL1 = bL0 + 16 * 144;

    float bch[8];
#pragma unroll
    for (int j = 0; j < 4; j++) {
        bch[j * 2]     = ((float*)(base + SGBIAS))[N0 + j * 8 + (lane & 3) * 2];
        bch[j * 2 + 1] = ((float*)(base + SGBIAS))[N0 + j * 8 + (lane & 3) * 2 + 1];
    }

    float C[2][4][4];
#pragma unroll
    for (int mi = 0; mi < 2; mi++)
#pragma unroll
        for (int j = 0; j < 4; j++)
#pragma unroll
            for (int p = 0; p < 4; p++) C[mi][j][p] = 0.0f;

#pragma unroll
    for (int ks = 0; ks < 4; ks++) {
        const uint32_t ko = (uint32_t)ks * 32u;
        uint32_t ah0[4], ah1[4], al0[4], al1[4], whA[4], whB[4], wlA[4], wlB[4];
        LDSM4(ah0, aH0 + ko); LDSM4(ah1, aH1 + ko);
        LDSM4(whA, bH0 + ko); LDSM4(whB, bH1 + ko);
        MMA16(C[0][0], ah0, whA + 0); MMA16(C[0][1], ah0, whA + 2);
        MMA16(C[0][2], ah0, whB + 0); MMA16(C[0][3], ah0, whB + 2);
        MMA16(C[1][0], ah1, whA + 0); MMA16(C[1][1], ah1, whA + 2);
        MMA16(C[1][2], ah1, whB + 0); MMA16(C[1][3], ah1, whB + 2);
        LDSM4(wlA, bL0 + ko); LDSM4(wlB, bL1 + ko);
        MMA16(C[0][0], ah0, wlA + 0); MMA16(C[0][1], ah0, wlA + 2);
        MMA16(C[0][2], ah0, wlB + 0); MMA16(C[0][3], ah0, wlB + 2);
        MMA16(C[1][0], ah1, wlA + 0); MMA16(C[1][1], ah1, wlA + 2);
        MMA16(C[1][2], ah1, wlB + 0); MMA16(C[1][3], ah1, wlB + 2);
        LDSM4(al0, aL0 + ko); LDSM4(al1, aL1 + ko);
        MMA16(C[0][0], al0, whA + 0); MMA16(C[0][1], al0, whA + 2);
        MMA16(C[0][2], al0, whB + 0); MMA16(C[0][3], al0, whB + 2);
        MMA16(C[1][0], al1, whA + 0); MMA16(C[1][1], al1, whA + 2);
        MMA16(C[1][2], al1, whB + 0); MMA16(C[1][3], al1, whB + 2);
    }

#pragma unroll
    for (int mi = 0; mi < 2; mi++) {
        int r0 = R0 + mi * 16 + (lane >> 2);
        int r1 = r0 + 8;
#pragma unroll
        for (int j = 0; j < 4; j++) {
            int col = N0 + j * 8 + (lane & 3) * 2;
            if (n0 + r0 < NA)
                *(__half2*)&g_self[(size_t)(n0 + r0) * CD + col] =
                    __floats2half2_rn(C[mi][j][0] + bch[j * 2],
                                      C[mi][j][1] + bch[j * 2 + 1]);
            if (n0 + r1 < NA)
                *(__half2*)&g_self[(size_t)(n0 + r1) * CD + col] =
                    __floats2half2_rn(C[mi][j][2] + bch[j * 2],
                                      C[mi][j][3] + bch[j * 2 + 1]);
        }
    }
}

// ---------------- convg: two independent 256-thread groups -------------------
// Group g (warps 8g..8g+7) streams 60-row (5-atom) tiles, double-buffered,
// against shared SMEM W. Named barriers keep groups independent so one
// group's stage/epilogue overlaps the other's MMAs.
__global__ void __launch_bounds__(512, 1) convg(const int* __restrict__ nidx,
                                                const float* __restrict__ Wl)
{
    extern __shared__ char smraw[];
    char* base = (char*)((((uintptr_t)smraw) + 1023) & ~(uintptr_t)1023);
    const uint32_t bu = smem_u32(base);

    const int tid = threadIdx.x, wid = tid >> 5, lane = tid & 31;
    const int g = tid >> 8;               // group 0/1
    const int gtid = tid & 255;
    const int gwid = wid & 7;
    const int warp_m = gwid & 1, warp_n = gwid >> 1;
    const int R0 = warp_m * 32, N0 = warp_n * 32;
    int* sIdx = (int*)(base + SIDX_OFF);

    for (int i = tid; i < (int)(SMEM_USED / 4); i += 512) ((uint32_t*)base)[i] = 0;
    __syncthreads();

    // W^T hi/lo for k_global 64..168 (local 0..104; 105..119 stay zero)
    for (int i = tid; i < 105 * 128; i += 512) {
        int k = i >> 7, c = i & 127;
        __nv_bfloat16 h, l;
        splitbf(Wl[(64 + k) * CD + c], h, l);
        *(__nv_bfloat16*)(base + WHI_OFF + c * ASTRB + k * 2) = h;
        *(__nv_bfloat16*)(base + WLO_OFF + c * ASTRB + k * 2) = l;
    }
    __syncthreads();

    // per-group staging: A hi/lo + self(fp16), cp.async
    auto STAGE = [&](int t, int sbuf) {
        const int rbase = t * TROWS;
        const int a0 = t * TATOMS;
        const int* sx = sIdx + (g * 2 + sbuf) * 64;
        const uint32_t dH = bu + GA_OFF + (uint32_t)(g * 2 + sbuf) * STG_B;
        const uint32_t dL = dH + 15360u;
        const uint32_t dS = dH + SELF_IN;
        for (int i = gtid; i < TROWS * 14 + 80; i += 256) {
            if (i < TROWS * 14) {
                int r = i / 14, c = i - r * 14;
                const char *sh, *sl;
                uint32_t doff;
                if (c < 8) {
                    size_t off = (size_t)sx[r] * 128 + c * 16;
                    sh = (const char*)g_AH + off; sl = (const char*)g_AL + off;
                    doff = (uint32_t)(r * ASTRB + c * 16);
                } else {
                    size_t off = (size_t)(rbase + r) * 96 + (c - 8) * 16;
                    sh = (const char*)g_NH + off; sl = (const char*)g_NL + off;
                    doff = (uint32_t)(r * ASTRB + 128 + (c - 8) * 16);
                }
                CPA16(dH + doff, sh);
                CPA16(dL + doff, sl);
            } else {
                int i2 = i - TROWS * 14;
                int a = i2 >> 4, c = i2 & 15;   // 5 atoms x 16 x 16B (fp16 self)
                CPA16(dS + (uint32_t)(a * 272 + c * 16),
                      (const char*)g_self + (size_t)(a0 + a) * 256 + c * 16);
            }
        }
    };

    const uint32_t aoffb = (uint32_t)(((R0 + (lane & 15)) * ASTRE + (lane >> 4) * 8) * 2);
    const uint32_t boffb = (uint32_t)(((N0 + (lane & 7) + (lane >> 4) * 8) * ASTRE
                                      + ((lane >> 3) & 1) * 8) * 2);
    const uint32_t bH0 = bu + WHI_OFF + boffb, bH1 = bH0 + 16 * ASTRB;
    const uint32_t bL0 = bu + WLO_OFF + boffb, bL1 = bL0 + 16 * ASTRB;

    float sS[8], sQ[8];
#pragma unroll
    for (int j = 0; j < 8; j++) { sS[j] = 0.0f; sQ[j] = 0.0f; }

    // ---- prologue ----
    int tile = blockIdx.x * 2 + g;
    if (gtid < TROWS) sIdx[(g * 2) * 64 + gtid] = nidx[tile * TROWS + gtid];
    GBAR(g);
    STAGE(tile, 0);
    CPA_COMMIT();
    int idxNext = 0;
    if (tile + TSTRD < NTILES && gtid < TROWS)
        idxNext = nidx[(tile + TSTRD) * TROWS + gtid];

    for (int it = 0; tile < NTILES; it++, tile += TSTRD) {
        const int nxt = tile + TSTRD;
        const int sb = it & 1;

        if (nxt < NTILES && gtid < TROWS)
            sIdx[(g * 2 + (sb ^ 1)) * 64 + gtid] = idxNext;
        GBAR(g);                       // prev GEMM done with buf sb^1; sIdx visible
        if (nxt < NTILES) STAGE(nxt, sb ^ 1);
        CPA_COMMIT();
        if (nxt + TSTRD < NTILES && gtid < TROWS)
            idxNext = nidx[(nxt + TSTRD) * TROWS + gtid];
        CPA_WAIT1();
        GBAR(g);

        const uint32_t AH = bu + GA_OFF + (uint32_t)(g * 2 + sb) * STG_B;
        const uint32_t AL = AH + 15360u;
        const uint32_t aH0 = AH + aoffb, aH1 = aH0 + 16 * ASTRB;
        const uint32_t aL0 = AL + aoffb, aL1 = aL0 + 16 * ASTRB;
        const char* selfB = base + GA_OFF + (size_t)(g * 2 + sb) * STG_B + SELF_IN;

        float C[2][4][4];
#pragma unroll
        for (int mi = 0; mi < 2; mi++)
#pragma unroll
            for (int j = 0; j < 4; j++)
#pragma unroll
                for (int p = 0; p < 4; p++) C[mi][j][p] = 0.0f;

#pragma unroll
        for (int ks = 0; ks < KSTEPS; ks++) {
            const uint32_t ko = (uint32_t)ks * 32u;
            uint32_t ah0[4], ah1[4], al0[4], al1[4], whA[4], whB[4], wlA[4], wlB[4];
            LDSM4(ah0, aH0 + ko); LDSM4(ah1, aH1 + ko);
            LDSM4(whA, bH0 + ko); LDSM4(whB, bH1 + ko);
            MMA16(C[0][0], ah0, whA + 0); MMA16(C[0][1], ah0, whA + 2);
            MMA16(C[0][2], ah0, whB + 0); MMA16(C[0][3], ah0, whB + 2);
            MMA16(C[1][0], ah1, whA + 0); MMA16(C[1][1], ah1, whA + 2);
            MMA16(C[1][2], ah1, whB + 0); MMA16(C[1][3], ah1, whB + 2);
            LDSM4(wlA, bL0 + ko); LDSM4(wlB, bL1 + ko);
            MMA16(C[0][0], ah0, wlA + 0); MMA16(C[0][1], ah0, wlA + 2);
            MMA16(C[0][2], ah0, wlB + 0); MMA16(C[0][3], ah0, wlB + 2);
            MMA16(C[1][0], ah1, wlA + 0); MMA16(C[1][1], ah1, wlA + 2);
            MMA16(C[1][2], ah1, wlB + 0); MMA16(C[1][3], ah1, wlB + 2);
            LDSM4(al0, aL0 + ko); LDSM4(al1, aL1 + ko);
            MMA16(C[0][0], al0, whA + 0); MMA16(C[0][1], al0, whA + 2);
            MMA16(C[0][2], al0, whB + 0); MMA16(C[0][3], al0, whB + 2);
            MMA16(C[1][0], al1, whA + 0); MMA16(C[1][1], al1, whA + 2);
            MMA16(C[1][2], al1, whB + 0); MMA16(C[1][3], al1, whB + 2);
        }

        // ---- epilogue: + self (fp16 SMEM), store gated fp16, stats ----
        const int growb = tile * TROWS;
#pragma unroll
        for (int mi = 0; mi < 2; mi++) {
            const int r0 = R0 + mi * 16 + (lane >> 2);
            const int r1 = r0 + 8;
            const bool v1 = (r1 < TROWS);     // rows 60..63 are pad
            const int a0l = r0 / MM;
            const int a1l = v1 ? (r1 / MM) : 0;
#pragma unroll
            for (int j = 0; j < 4; j++) {
                const int col = N0 + j * 8 + (lane & 3) * 2;
                float2 s0 = __half22float2(
                    *(const __half2*)(selfB + a0l * 272 + col * 2));
                float g0 = C[mi][j][0] + s0.x;
                float g1 = C[mi][j][1] + s0.y;
                *(__half2*)&g_gated[(size_t)(growb + r0) * CD + col] =
                    __floats2half2_rn(g0, g1);
                sS[j * 2] += g0; sS[j * 2 + 1] += g1;
                sQ[j * 2] = fmaf(g0, g0, sQ[j * 2]);
                sQ[j * 2 + 1] = fmaf(g1, g1, sQ[j * 2 + 1]);
                if (v1) {
                    float2 s1 = __half22float2(
                        *(const __half2*)(selfB + a1l * 272 + col * 2));
                    float g2 = C[mi][j][2] + s1.x;
                    float g3 = C[mi][j][3] + s1.y;
                    *(__half2*)&g_gated[(size_t)(growb + r1) * CD + col] =
                        __floats2half2_rn(g2, g3);
                    sS[j * 2] += g2; sS[j * 2 + 1] += g3;
                    sQ[j * 2] = fmaf(g2, g2, sQ[j * 2]);
                    sQ[j * 2 + 1] = fmaf(g3, g3, sQ[j * 2 + 1]);
                }
            }
        }
    }

    // ---- deterministic per-block stat reduction (overlay stages) ----
    __syncthreads();      // both groups done
    {
        float* sredS = (float*)(base + SREDS_OFF);   // [128][33]
        float* sredQ = (float*)(base + SREDQ_OFF);
        const int idx = (g * 2 + warp_m) * 8 + (lane >> 2);   // 0..31
#pragma unroll
        for (int j = 0; j < 4; j++)
#pragma unroll
            for (int e = 0; e < 2; e++) {
                int c = N0 + j * 8 + (lane & 3) * 2 + e;
                sredS[c * 33 + idx] = sS[j * 2 + e];
                sredQ[c * 33 + idx] = sQ[j * 2 + e];
            }
        __syncthreads();
        if (tid < 256) {
            int stat = tid >> 7, c = tid & 127;
            const float* p = stat ? sredQ : sredS;
            float v = 0.0f;
#pragma unroll
            for (int w = 0; w < 32; w++) v += p[c * 33 + w];
            g_part1[blockIdx.x * 2 * CD + tid] = v;
        }
    }
}

// ---------------- streaming pass2 (half2, 2 channels/thread) -----------------
__global__ void __launch_bounds__(256) pass2s_k() {
    const int tid = threadIdx.x;
    const int w0 = blockIdx.x * 256 + tid;        // item = (atom, channel-pair)
    const int cp = w0 & 31;                        // constant across grid stride
    const int c = cp * 2;
    const float scF0 = g_sc1[c],      shF0 = g_sh1[c];
    const float scF1 = g_sc1[c + 1],  shF1 = g_sh1[c + 1];
    const float scC0 = g_sc1[64 + c], shC0 = g_sh1[64 + c];
    const float scC1 = g_sc1[65 + c], shC1 = g_sh1[65 + c];

    float ss0 = 0, ss1 = 0, sq0 = 0, sq1 = 0;
    for (int o = w0; o < NA * 32; o += G2BLK * 256) {
        const int n = o >> 5;
        const __half* gp = g_gated + (size_t)n * (MM * CD);
        float s0 = 0.0f, s1 = 0.0f;
#pragma unroll
        for (int m = 0; m < MM; m++) {
            float2 f2 = __half22float2(*(const __half2*)&gp[m * CD + c]);
            float2 c2 = __half22float2(*(const __half2*)&gp[m * CD + 64 + c]);
            float f0 = fmaf(f2.x, scF0, shF0), f1 = fmaf(f2.y, scF1, shF1);
            float o0 = fmaf(c2.x, scC0, shC0), o1 = fmaf(c2.y, scC1, shC1);
            s0 += sigm(f0) * sftp(o0);
            s1 += sigm(f1) * sftp(o1);
        }
        *(float2*)&g_summed[(size_t)n * AFD + c] = make_float2(s0, s1);
        ss0 += s0; ss1 += s1;
        sq0 = fmaf(s0, s0, sq0); sq1 = fmaf(s1, s1, sq1);
    }

    __shared__ float sr[4][256];
    sr[0][tid] = ss0; sr[1][tid] = ss1; sr[2][tid] = sq0; sr[3][tid] = sq1;
    __syncthreads();
    if (tid < 128) {
        int st = tid >> 6, ch = tid & 63;
        int cpair = ch >> 1, e = ch & 1;
        const float* p = sr[st * 2 + e];
        float v = 0.0f;
#pragma unroll
        for (int q = 0; q < 8; q++) v += p[q * 32 + cpair];
        g_part2[blockIdx.x * 128 + tid] = v;
    }
}

// ---------------- BN finalize ------------------------------------------------
__global__ void __launch_bounds__(512) fin1_k(const float* __restrict__ g,
                                              const float* __restrict__ b) {
    __shared__ float sm[2][512];
    int tid = threadIdx.x, c = tid & 127, grp = tid >> 7;
    float s = 0, q = 0;
    for (int bl = grp; bl < NBLK; bl += 4) {
        s += g_part1[bl * 2 * CD + c];
        q += g_part1[bl * 2 * CD + CD + c];
    }
    sm[0][tid] = s; sm[1][tid] = q;
    __syncthreads();
    if (tid < 128) {
        float S = sm[0][tid] + sm[0][128 + tid] + sm[0][256 + tid] + sm[0][384 + tid];
        float Q = sm[1][tid] + sm[1][128 + tid] + sm[1][256 + tid] + sm[1][384 + tid];
        const float inv = 1.0f / ((float)NA * (float)MM);
        float mu = S * inv;
        float var = Q * inv - mu * mu;
        float sc = g[tid] * rsqrtf(var + EPSV);
        g_sc1[tid] = sc;
        g_sh1[tid] = b[tid] - mu * sc;
    }
}
__global__ void __launch_bounds__(512) fin2_k(const float* __restrict__ g,
                                              const float* __restrict__ b) {
    __shared__ float sm[2][512];
    int tid = threadIdx.x, c = tid & 63, grp = tid >> 6;
    float s = 0, q = 0;
    for (int bl = grp; bl < G2BLK; bl += 8) {
        s += g_part2[bl * 128 + c];
        q += g_part2[bl * 128 + 64 + c];
    }
    sm[0][tid] = s; sm[1][tid] = q;
    __syncthreads();
    if (tid < 64) {
        float S = 0, Q = 0;
#pragma unroll
        for (int w = 0; w < 8; w++) { S += sm[0][w * 64 + tid]; Q += sm[1][w * 64 + tid]; }
        const float inv = 1.0f / (float)NA;
        float mu = S * inv;
        float var = Q * inv - mu * mu;
        float sc = g[tid] * rsqrtf(var + EPSV);
        g_sc2[tid] = sc;
        g_sh2[tid] = b[tid] - mu * sc;
    }
}

// ---------------- residual + bn2 + softplus (+ bf16 hi/lo) -------------------
__global__ void update_k(const float* __restrict__ fin, float* __restrict__ fout) {
    int i = blockIdx.x * blockDim.x + threadIdx.x;
    if (i < NA * AFD) {
        int c = i & 63;
        float v = sftp(fin[i] + fmaf(g_summed[i], g_sc2[c], g_sh2[c]));
        fout[i] = v;
        splitbf(v, g_AH[i], g_AL[i]);
    }
}

// ---------------- head -------------------------------------------------------
__global__ void head_k(const float* __restrict__ afea, const int* __restrict__ cai,
                       const float* __restrict__ Wfc, const float* __restrict__ bfc,
                       const float* __restrict__ Wout, const float* __restrict__ bout,
                       float* __restrict__ out) {
    __shared__ float scry[AFD];
    __shared__ float shid[HF];
    __shared__ float part[2][AFD];
    int b = blockIdx.x, t = threadIdx.x;
    int c = t & 63, h = t >> 6;

    const int* idx = cai + b * APC;
    float acc = 0;
    for (int a = h * (APC / 2); a < (h + 1) * (APC / 2); a++)
        acc += afea[idx[a] * AFD + c];
    part[h][c] = acc;
    __syncthreads();

    if (t < AFD) scry[t] = sftp((part[0][t] + part[1][t]) * (1.0f / (float)APC));
    __syncthreads();

    float a2 = bfc[t];
    for (int k = 0; k < AFD; k++) a2 = fmaf(scry[k], Wfc[k * HF + t], a2);
    shid[t] = sftp(a2);
    __syncthreads();

    if (t < HID) {
        float a3 = bout[t];
        for (int k = 0; k < HF; k++) a3 = fmaf(shid[k], Wout[k * HID + t], a3);
        out[b * HID + t] = a3;
    }
}

// ---------------- launch -----------------------------------------------------
extern "C" void kernel_launch(void* const* d_in, const int* in_sizes, int n_in,
                              void* d_out, int out_size) {
    const int*   atom_num = (const int*)d_in[0];
    const float* nbr_fea  = (const float*)d_in[1];
    const int*   nidx     = (const int*)d_in[2];
    const int*   cai      = (const int*)d_in[3];
    const float* emb      = (const float*)d_in[4];
    const float* W_full   = (const float*)d_in[5];
    const float* b_full   = (const float*)d_in[6];
    const float* bn1g     = (const float*)d_in[7];
    const float* bn1b     = (const float*)d_in[8];
    const float* bn2g     = (const float*)d_in[9];
    const float* bn2b     = (const float*)d_in[10];
    const float* Wfc      = (const float*)d_in[11];
    const float* bfc      = (const float*)d_in[12];
    const float* Wout     = (const float*)d_in[13];
    const float* bout     = (const float*)d_in[14];
    float* out = (float*)d_out;

    cudaFuncSetAttribute(convg,   cudaFuncAttributeMaxDynamicSharedMemorySize, SMEM_DYN);
    cudaFuncSetAttribute(selfg_k, cudaFuncAttributeMaxDynamicSharedMemorySize, SG_DYN);

    void *p0, *p1;
    cudaGetSymbolAddress(&p0, g_fea0);
    cudaGetSymbolAddress(&p1, g_fea1);
    float* fin  = (float*)p0;
    float* fout = (float*)p1;

    embed2_k<<<(NA * AFD + 255) / 256, 256>>>(atom_num, emb);
    nbrcvt_k<<<(NA * MM * NFP + 255) / 256, 256>>>(nbr_fea);

    for (int i = 0; i < NCONV; i++) {
        const float* Wlp = W_full + (size_t)i * KD * CD;
        const float* blp = b_full + (size_t)i * CD;
        selfg_k<<<(NA + 127) / 128, 512, SG_DYN>>>(Wlp, blp);
        convg<<<NBLK, 512, SMEM_DYN>>>(nidx, Wlp);
        fin1_k<<<1, 512>>>(bn1g + (size_t)i * CD, bn1b + (size_t)i * CD);
        pass2s_k<<<G2BLK, 256>>>();
        fin2_k<<<1, 512>>>(bn2g + (size_t)i * AFD, bn2b + (size_t)i * AFD);
        update_k<<<(NA * AFD + 255) / 256, 256>>>(fin, fout);
        float* tmp = fin; fin = fout; fout = tmp;
    }

    head_k<<<NCRY, 128>>>(fin, cai, Wfc, bfc, Wout, bout, out);
}

// round 15
// speedup vs baseline: 1.9906x; 1.9906x over previous
#include <cuda_runtime.h>
#include <cuda_fp16.h>
#include <cstdint>

#define NA   100000
#define MM   12
#define AFD  64
#define NFD  41
#define KD   169
#define CD   128
#define NCONV 3
#define NCRY 100
#define APC  1000
#define HF   128
#define HID  64
#define EPSV 1e-5f

#define NBLK2  296             // convg grid (2 CTAs/SM)
#define TATOMS 5
#define NTILES (NA / TATOMS)   // 20000
#define TROWS  60
#define KSTEPS 7               // K_rest = 112 (64 nbr + 48 bond-pad)
#define ASTRE  120
#define ASTRB  240
#define NFP    48

#define G2BLK  1184

// ---- convg SMEM byte offsets (from 1024-aligned base) ----
#define W_OFF     0u           // 128 ch x 120 k x 2B (k 105..119 zero)
#define GA_OFF    30720u       // 2 stages x STG_B
#define STG_B     16000u       // A 14400 | self 1360 | pad
#define SELF_IN   14400u
#define SIDX_OFF  62720u       // 2 x 64 i32
#define SMEM_USED 63232u
#define SMEM_DYN  (SMEM_USED + 1024u)
// stat-reduction overlay (after mainloop)
#define SREDS_OFF GA_OFF
#define SREDQ_OFF (GA_OFF + 8704u)

// ---- selfg SMEM ----
#define SGA_OFF 0u             // 128 rows x 144B
#define SGW_OFF 18432u         // 128 ch x 144B
#define SGBIAS  36864u
#define SG_USED 37376u
#define SG_DYN  (SG_USED + 1024u)

typedef unsigned long long ull;

// ---------------- scratch (device globals) ----------------------------------
__device__ float g_fea0[NA * AFD];
__device__ float g_fea1[NA * AFD];
__device__ float g_summed[NA * AFD];
__device__ __half g_gated[NA * MM * CD];         // 307 MB fp16
__device__ __half g_self[NA * CD];               // 25.6 MB fp16
__device__ __half g_AF[NA * AFD];                // fp16 atom features
__device__ __half g_NF[NA * MM * NFP];           // fp16 bond features (padded)
__device__ float g_part1[NBLK2 * 2 * CD];
__device__ float g_part2[G2BLK * 2 * AFD];
__device__ float g_sc1[CD], g_sh1[CD];
__device__ float g_sc2[AFD], g_sh2[AFD];

// ---------------- helpers ----------------------------------------------------
__device__ __forceinline__ uint32_t smem_u32(const void* p) {
    uint32_t a;
    asm("{ .reg .u64 t; cvta.to.shared.u64 t, %1; cvt.u32.u64 %0, t; }"
        : "=r"(a) : "l"(p));
    return a;
}

#define LDSM4(r, addr) \
    asm volatile("ldmatrix.sync.aligned.m8n8.x4.shared.b16 {%0,%1,%2,%3},[%4];" \
        : "=r"((r)[0]), "=r"((r)[1]), "=r"((r)[2]), "=r"((r)[3]) : "r"(addr))

#define MMAH(c, a, b) \
    asm volatile("mma.sync.aligned.m16n8k16.row.col.f32.f16.f16.f32 " \
        "{%0,%1,%2,%3},{%4,%5,%6,%7},{%8,%9},{%0,%1,%2,%3};" \
        : "+f"((c)[0]), "+f"((c)[1]), "+f"((c)[2]), "+f"((c)[3]) \
        : "r"((a)[0]), "r"((a)[1]), "r"((a)[2]), "r"((a)[3]), \
          "r"((b)[0]), "r"((b)[1]))

#define CPA16(dst, src) \
    asm volatile("cp.async.cg.shared.global [%0],[%1],16;" \
        :: "r"(dst), "l"(src) : "memory")
#define CPA_COMMIT() asm volatile("cp.async.commit_group;" ::: "memory")
#define CPA_WAIT1()  asm volatile("cp.async.wait_group 1;" ::: "memory")

__device__ __forceinline__ float sigm(float x) {
    return __fdividef(1.0f, 1.0f + __expf(-x));
}
__device__ __forceinline__ float sftp(float x) {
    return fmaxf(x, 0.0f) + __logf(1.0f + __expf(-fabsf(x)));
}

// ---------------- embedding + bond preconversion -----------------------------
__global__ void embed2_k(const int* __restrict__ an, const float* __restrict__ emb) {
    int i = blockIdx.x * blockDim.x + threadIdx.x;
    if (i < NA * AFD) {
        int n = i >> 6, c = i & 63;
        float v = emb[an[n] * AFD + c];
        g_fea0[i] = v;
        g_AF[i] = __float2half(v);
    }
}
__global__ void nbrcvt_k(const float* __restrict__ nbrf) {
    int i = blockIdx.x * blockDim.x + threadIdx.x;
    if (i < NA * MM * NFP) {
        int r = i / NFP, k = i - r * NFP;
        float v = (k < NFD) ? nbrf[r * NFD + k] : 0.0f;
        g_NF[i] = __float2half(v);
    }
}

// ---------------- selfg: S = atom_fea @ W[0:64] + bias -> fp16 ---------------
// 128 rows x 128 ch, K=64, single-term fp16 MMA.
__global__ void __launch_bounds__(512, 1) selfg_k(
    const float* __restrict__ Wl, const float* __restrict__ bl)
{
    extern __shared__ char smraw[];
    char* base = (char*)((((uintptr_t)smraw) + 1023) & ~(uintptr_t)1023);
    const uint32_t bu = smem_u32(base);

    const int tid = threadIdx.x, wid = tid >> 5, lane = tid & 31;
    const int warp_m = wid & 3, warp_n = wid >> 2;
    const int R0 = warp_m * 32, N0 = warp_n * 32;
    const int n0 = blockIdx.x * 128;

    // stage A (fp16, guarded), 144B row stride
    for (int i = tid; i < 128 * 8; i += 512) {
        int r = i >> 3, c = i & 7;
        uint4 v = make_uint4(0, 0, 0, 0);
        if (n0 + r < NA)
            v = *(const uint4*)((const char*)g_AF + (size_t)(n0 + r) * 128 + c * 16);
        *(uint4*)(base + SGA_OFF + r * 144 + c * 16) = v;
    }
    // stage W^T fp16 (rows = channels, k = 0..63)
    for (int i = tid; i < 64 * 128; i += 512) {
        int k = i >> 7, c = i & 127;
        *(__half*)(base + SGW_OFF + c * 144 + k * 2) = __float2half(Wl[k * CD + c]);
    }
    if (tid < 128) ((float*)(base + SGBIAS))[tid] = bl[tid];
    __syncthreads();

    const uint32_t aoffb = (uint32_t)(((R0 + (lane & 15)) * 72 + (lane >> 4) * 8) * 2);
    const uint32_t aT0 = bu + SGA_OFF + aoffb, aT1 = aT0 + 16 * 144;
    const uint32_t boffb = (uint32_t)(((N0 + (lane & 7) + (lane >> 4) * 8) * 72
                                      + ((lane >> 3) & 1) * 8) * 2);
    const uint32_t bA = bu + SGW_OFF + boffb, bB = bA + 16 * 144;

    float bch[8];
#pragma unroll
    for (int j = 0; j < 4; j++) {
        bch[j * 2]     = ((float*)(base + SGBIAS))[N0 + j * 8 + (lane & 3) * 2];
        bch[j * 2 + 1] = ((float*)(base + SGBIAS))[N0 + j * 8 + (lane & 3) * 2 + 1];
    }

    float C[2][4][4];
#pragma unroll
    for (int mi = 0; mi < 2; mi++)
#pragma unroll
        for (int j = 0; j < 4; j++)
#pragma unroll
            for (int p = 0; p < 4; p++) C[mi][j][p] = 0.0f;

#pragma unroll
    for (int ks = 0; ks < 4; ks++) {
        const uint32_t ko = (uint32_t)ks * 32u;
        uint32_t a0[4], a1[4], wA[4], wB[4];
        LDSM4(a0, aT0 + ko); LDSM4(a1, aT1 + ko);
        LDSM4(wA, bA + ko);  LDSM4(wB, bB + ko);
        MMAH(C[0][0], a0, wA + 0); MMAH(C[0][1], a0, wA + 2);
        MMAH(C[0][2], a0, wB + 0); MMAH(C[0][3], a0, wB + 2);
        MMAH(C[1][0], a1, wA + 0); MMAH(C[1][1], a1, wA + 2);
        MMAH(C[1][2], a1, wB + 0); MMAH(C[1][3], a1, wB + 2);
    }

#pragma unroll
    for (int mi = 0; mi < 2; mi++) {
        int r0 = R0 + mi * 16 + (lane >> 2);
        int r1 = r0 + 8;
#pragma unroll
        for (int j = 0; j < 4; j++) {
            int col = N0 + j * 8 + (lane & 3) * 2;
            if (n0 + r0 < NA)
                *(__half2*)&g_self[(size_t)(n0 + r0) * CD + col] =
                    __floats2half2_rn(C[mi][j][0] + bch[j * 2],
                                      C[mi][j][1] + bch[j * 2 + 1]);
            if (n0 + r1 < NA)
                *(__half2*)&g_self[(size_t)(n0 + r1) * CD + col] =
                    __floats2half2_rn(C[mi][j][2] + bch[j * 2],
                                      C[mi][j][3] + bch[j * 2 + 1]);
        }
    }
}

// ---------------- convg: single-term fp16 rest-GEMM (K=112) ------------------
// 256 threads, 2 CTAs/SM. Tile 60 rows (5 atoms) x 128 ch, double-buffered.
__global__ void __launch_bounds__(256, 2) convg(const int* __restrict__ nidx,
                                                const float* __restrict__ Wl)
{
    extern __shared__ char smraw[];
    char* base = (char*)((((uintptr_t)smraw) + 1023) & ~(uintptr_t)1023);
    const uint32_t bu = smem_u32(base);

    const int tid = threadIdx.x, wid = tid >> 5, lane = tid & 31;
    const int warp_m = wid & 1, warp_n = wid >> 1;
    const int R0 = warp_m * 32, N0 = warp_n * 32;
    int* sIdx = (int*)(base + SIDX_OFF);

    for (int i = tid; i < (int)(SMEM_USED / 4); i += 256) ((uint32_t*)base)[i] = 0;
    __syncthreads();

    // W^T fp16 for k_global 64..168 (local 0..104; 105..119 stay zero)
    for (int i = tid; i < 105 * 128; i += 256) {
        int k = i >> 7, c = i & 127;
        *(__half*)(base + W_OFF + c * ASTRB + k * 2) = __float2half(Wl[(64 + k) * CD + c]);
    }

    int tile = blockIdx.x;
    if (tid < TROWS) sIdx[tid] = nidx[tile * TROWS + tid];
    __syncthreads();

    // staging: A fp16 (nbr 128B + bond 96B per row) + self fp16 (256B/atom)
    auto STAGE = [&](int t, int sbuf) {
        const int rbase = t * TROWS;
        const int a0 = t * TATOMS;
        const int* sx = sIdx + sbuf * 64;
        const uint32_t dA = bu + GA_OFF + (uint32_t)sbuf * STG_B;
        const uint32_t dS = dA + SELF_IN;
        for (int i = tid; i < TROWS * 14 + 80; i += 256) {
            if (i < TROWS * 14) {
                int r = i / 14, c = i - r * 14;
                const char* src;
                uint32_t doff;
                if (c < 8) {
                    src = (const char*)g_AF + (size_t)sx[r] * 128 + c * 16;
                    doff = (uint32_t)(r * ASTRB + c * 16);
                } else {
                    src = (const char*)g_NF + (size_t)(rbase + r) * 96 + (c - 8) * 16;
                    doff = (uint32_t)(r * ASTRB + 128 + (c - 8) * 16);
                }
                CPA16(dA + doff, src);
            } else {
                int i2 = i - TROWS * 14;
                int a = i2 >> 4, c = i2 & 15;    // 5 atoms x 16 x 16B
                CPA16(dS + (uint32_t)(a * 272 + c * 16),
                      (const char*)g_self + (size_t)(a0 + a) * 256 + c * 16);
            }
        }
    };

    STAGE(tile, 0);
    CPA_COMMIT();
    int idxNext = 0;
    if (tile + NBLK2 < NTILES && tid < TROWS)
        idxNext = nidx[(tile + NBLK2) * TROWS + tid];

    const uint32_t aoffb = (uint32_t)(((R0 + (lane & 15)) * ASTRE + (lane >> 4) * 8) * 2);
    const uint32_t boffb = (uint32_t)(((N0 + (lane & 7) + (lane >> 4) * 8) * ASTRE
                                      + ((lane >> 3) & 1) * 8) * 2);
    const uint32_t bA = bu + W_OFF + boffb, bB = bA + 16 * ASTRB;

    float sS[8], sQ[8];
#pragma unroll
    for (int j = 0; j < 8; j++) { sS[j] = 0.0f; sQ[j] = 0.0f; }

    for (int it = 0; tile < NTILES; it++, tile += NBLK2) {
        const int nxt = tile + NBLK2;
        const int sb = it & 1;

        if (nxt < NTILES && tid < TROWS)
            sIdx[(sb ^ 1) * 64 + tid] = idxNext;
        __syncthreads();               // prev GEMM done with buf sb^1; sIdx visible
        if (nxt < NTILES) STAGE(nxt, sb ^ 1);
        CPA_COMMIT();
        if (nxt + NBLK2 < NTILES && tid < TROWS)
            idxNext = nidx[(nxt + NBLK2) * TROWS + tid];
        CPA_WAIT1();
        __syncthreads();

        const uint32_t dA = bu + GA_OFF + (uint32_t)sb * STG_B;
        const uint32_t aT0 = dA + aoffb, aT1 = aT0 + 16 * ASTRB;
        const char* selfB = base + GA_OFF + (size_t)sb * STG_B + SELF_IN;

        float C[2][4][4];
#pragma unroll
        for (int mi = 0; mi < 2; mi++)
#pragma unroll
            for (int j = 0; j < 4; j++)
#pragma unroll
                for (int p = 0; p < 4; p++) C[mi][j][p] = 0.0f;

#pragma unroll
        for (int ks = 0; ks < KSTEPS; ks++) {
            const uint32_t ko = (uint32_t)ks * 32u;
            uint32_t a0[4], a1[4], wA[4], wB[4];
            LDSM4(a0, aT0 + ko); LDSM4(a1, aT1 + ko);
            LDSM4(wA, bA + ko);  LDSM4(wB, bB + ko);
            MMAH(C[0][0], a0, wA + 0); MMAH(C[0][1], a0, wA + 2);
            MMAH(C[0][2], a0, wB + 0); MMAH(C[0][3], a0, wB + 2);
            MMAH(C[1][0], a1, wA + 0); MMAH(C[1][1], a1, wA + 2);
            MMAH(C[1][2], a1, wB + 0); MMAH(C[1][3], a1, wB + 2);
        }

        // ---- epilogue: + self (fp16 SMEM), store gated fp16, stats ----
        const int growb = tile * TROWS;
#pragma unroll
        for (int mi = 0; mi < 2; mi++) {
            const int r0 = R0 + mi * 16 + (lane >> 2);
            const int r1 = r0 + 8;
            const bool v1 = (r1 < TROWS);     // rows 60..63 are pad
            const int a0l = r0 / MM;
            const int a1l = v1 ? (r1 / MM) : 0;
#pragma unroll
            for (int j = 0; j < 4; j++) {
                const int col = N0 + j * 8 + (lane & 3) * 2;
                float2 s0 = __half22float2(
                    *(const __half2*)(selfB + a0l * 272 + col * 2));
                float g0 = C[mi][j][0] + s0.x;
                float g1 = C[mi][j][1] + s0.y;
                *(__half2*)&g_gated[(size_t)(growb + r0) * CD + col] =
                    __floats2half2_rn(g0, g1);
                sS[j * 2] += g0; sS[j * 2 + 1] += g1;
                sQ[j * 2] = fmaf(g0, g0, sQ[j * 2]);
                sQ[j * 2 + 1] = fmaf(g1, g1, sQ[j * 2 + 1]);
                if (v1) {
                    float2 s1 = __half22float2(
                        *(const __half2*)(selfB + a1l * 272 + col * 2));
                    float g2 = C[mi][j][2] + s1.x;
                    float g3 = C[mi][j][3] + s1.y;
                    *(__half2*)&g_gated[(size_t)(growb + r1) * CD + col] =
                        __floats2half2_rn(g2, g3);
                    sS[j * 2] += g2; sS[j * 2 + 1] += g3;
                    sQ[j * 2] = fmaf(g2, g2, sQ[j * 2]);
                    sQ[j * 2 + 1] = fmaf(g3, g3, sQ[j * 2 + 1]);
                }
            }
        }
    }

    // ---- deterministic per-block stat reduction (overlay stages) ----
    __syncthreads();
    {
        float* sredS = (float*)(base + SREDS_OFF);   // [128][17]
        float* sredQ = (float*)(base + SREDQ_OFF);
        const int idx = warp_m * 8 + (lane >> 2);    // 0..15
#pragma unroll
        for (int j = 0; j < 4; j++)
#pragma unroll
            for (int e = 0; e < 2; e++) {
                int c = N0 + j * 8 + (lane & 3) * 2 + e;
                sredS[c * 17 + idx] = sS[j * 2 + e];
                sredQ[c * 17 + idx] = sQ[j * 2 + e];
            }
        __syncthreads();
        // 256 threads: stat = tid>>7, c = tid&127
        int stat = tid >> 7, c = tid & 127;
        const float* p = stat ? sredQ : sredS;
        float v = 0.0f;
#pragma unroll
        for (int w = 0; w < 16; w++) v += p[c * 17 + w];
        g_part1[blockIdx.x * 2 * CD + tid] = v;
    }
}

// ---------------- streaming pass2 (half2, 2 channels/thread) -----------------
__global__ void __launch_bounds__(256) pass2s_k() {
    const int tid = threadIdx.x;
    const int w0 = blockIdx.x * 256 + tid;
    const int cp = w0 & 31;                        // invariant across grid stride
    const int c = cp * 2;
    const float scF0 = g_sc1[c],      shF0 = g_sh1[c];
    const float scF1 = g_sc1[c + 1],  shF1 = g_sh1[c + 1];
    const float scC0 = g_sc1[64 + c], shC0 = g_sh1[64 + c];
    const float scC1 = g_sc1[65 + c], shC1 = g_sh1[65 + c];

    float ss0 = 0, ss1 = 0, sq0 = 0, sq1 = 0;
    for (int o = w0; o < NA * 32; o += G2BLK * 256) {
        const int n = o >> 5;
        const __half* gp = g_gated + (size_t)n * (MM * CD);
        float s0 = 0.0f, s1 = 0.0f;
#pragma unroll
        for (int m = 0; m < MM; m++) {
            float2 f2 = __half22float2(*(const __half2*)&gp[m * CD + c]);
            float2 c2 = __half22float2(*(const __half2*)&gp[m * CD + 64 + c]);
            float f0 = fmaf(f2.x, scF0, shF0), f1 = fmaf(f2.y, scF1, shF1);
            float o0 = fmaf(c2.x, scC0, shC0), o1 = fmaf(c2.y, scC1, shC1);
            s0 += sigm(f0) * sftp(o0);
            s1 += sigm(f1) * sftp(o1);
        }
        *(float2*)&g_summed[(size_t)n * AFD + c] = make_float2(s0, s1);
        ss0 += s0; ss1 += s1;
        sq0 = fmaf(s0, s0, sq0); sq1 = fmaf(s1, s1, sq1);
    }

    __shared__ float sr[4][256];
    sr[0][tid] = ss0; sr[1][tid] = ss1; sr[2][tid] = sq0; sr[3][tid] = sq1;
    __syncthreads();
    if (tid < 128) {
        int st = tid >> 6, ch = tid & 63;
        int cpair = ch >> 1, e = ch & 1;
        const float* p = sr[st * 2 + e];
        float v = 0.0f;
#pragma unroll
        for (int q = 0; q < 8; q++) v += p[q * 32 + cpair];
        g_part2[blockIdx.x * 128 + tid] = v;
    }
}

// ---------------- BN finalize ------------------------------------------------
__global__ void __launch_bounds__(512) fin1_k(const float* __restrict__ g,
                                              const float* __restrict__ b) {
    __shared__ float sm[2][512];
    int tid = threadIdx.x, c = tid & 127, grp = tid >> 7;
    float s = 0, q = 0;
    for (int bl = grp; bl < NBLK2; bl += 4) {
        s += g_part1[bl * 2 * CD + c];
        q += g_part1[bl * 2 * CD + CD + c];
    }
    sm[0][tid] = s; sm[1][tid] = q;
    __syncthreads();
    if (tid < 128) {
        float S = sm[0][tid] + sm[0][128 + tid] + sm[0][256 + tid] + sm[0][384 + tid];
        float Q = sm[1][tid] + sm[1][128 + tid] + sm[1][256 + tid] + sm[1][384 + tid];
        const float inv = 1.0f / ((float)NA * (float)MM);
        float mu = S * inv;
        float var = Q * inv - mu * mu;
        float sc = g[tid] * rsqrtf(var + EPSV);
        g_sc1[tid] = sc;
        g_sh1[tid] = b[tid] - mu * sc;
    }
}
__global__ void __launch_bounds__(512) fin2_k(const float* __restrict__ g,
                                              const float* __restrict__ b) {
    __shared__ float sm[2][512];
    int tid = threadIdx.x, c = tid & 63, grp = tid >> 6;
    float s = 0, q = 0;
    for (int bl = grp; bl < G2BLK; bl += 8) {
        s += g_part2[bl * 128 + c];
        q += g_part2[bl * 128 + 64 + c];
    }
    sm[0][tid] = s; sm[1][tid] = q;
    __syncthreads();
    if (tid < 64) {
        float S = 0, Q = 0;
#pragma unroll
        for (int w = 0; w < 8; w++) { S += sm[0][w * 64 + tid]; Q += sm[1][w * 64 + tid]; }
        const float inv = 1.0f / (float)NA;
        float mu = S * inv;
        float var = Q * inv - mu * mu;
        float sc = g[tid] * rsqrtf(var + EPSV);
        g_sc2[tid] = sc;
        g_sh2[tid] = b[tid] - mu * sc;
    }
}

// ---------------- residual + bn2 + softplus (+ fp16 features) ----------------
__global__ void update_k(const float* __restrict__ fin, float* __restrict__ fout) {
    int i = blockIdx.x * blockDim.x + threadIdx.x;
    if (i < NA * AFD) {
        int c = i & 63;
        float v = sftp(fin[i] + fmaf(g_summed[i], g_sc2[c], g_sh2[c]));
        fout[i] = v;
        g_AF[i] = __float2half(v);
    }
}

// ---------------- head -------------------------------------------------------
__global__ void head_k(const float* __restrict__ afea, const int* __restrict__ cai,
                       const float* __restrict__ Wfc, const float* __restrict__ bfc,
                       const float* __restrict__ Wout, const float* __restrict__ bout,
                       float* __restrict__ out) {
    __shared__ float scry[AFD];
    __shared__ float shid[HF];
    __shared__ float part[2][AFD];
    int b = blockIdx.x, t = threadIdx.x;
    int c = t & 63, h = t >> 6;

    const int* idx = cai + b * APC;
    float acc = 0;
    for (int a = h * (APC / 2); a < (h + 1) * (APC / 2); a++)
        acc += afea[idx[a] * AFD + c];
    part[h][c] = acc;
    __syncthreads();

    if (t < AFD) scry[t] = sftp((part[0][t] + part[1][t]) * (1.0f / (float)APC));
    __syncthreads();

    float a2 = bfc[t];
    for (int k = 0; k < AFD; k++) a2 = fmaf(scry[k], Wfc[k * HF + t], a2);
    shid[t] = sftp(a2);
    __syncthreads();

    if (t < HID) {
        float a3 = bout[t];
        for (int k = 0; k < HF; k++) a3 = fmaf(shid[k], Wout[k * HID + t], a3);
        out[b * HID + t] = a3;
    }
}

// ---------------- launch -----------------------------------------------------
extern "C" void kernel_launch(void* const* d_in, const int* in_sizes, int n_in,
                              void* d_out, int out_size) {
    const int*   atom_num = (const int*)d_in[0];
    const float* nbr_fea  = (const float*)d_in[1];
    const int*   nidx     = (const int*)d_in[2];
    const int*   cai      = (const int*)d_in[3];
    const float* emb      = (const float*)d_in[4];
    const float* W_full   = (const float*)d_in[5];
    const float* b_full   = (const float*)d_in[6];
    const float* bn1g     = (const float*)d_in[7];
    const float* bn1b     = (const float*)d_in[8];
    const float* bn2g     = (const float*)d_in[9];
    const float* bn2b     = (const float*)d_in[10];
    const float* Wfc      = (const float*)d_in[11];
    const float* bfc      = (const float*)d_in[12];
    const float* Wout     = (const float*)d_in[13];
    const float* bout     = (const float*)d_in[14];
    float* out = (float*)d_out;

    cudaFuncSetAttribute(convg,   cudaFuncAttributeMaxDynamicSharedMemorySize, SMEM_DYN);
    cudaFuncSetAttribute(selfg_k, cudaFuncAttributeMaxDynamicSharedMemorySize, SG_DYN);

    void *p0, *p1;
    cudaGetSymbolAddress(&p0, g_fea0);
    cudaGetSymbolAddress(&p1, g_fea1);
    float* fin  = (float*)p0;
    float* fout = (float*)p1;

    embed2_k<<<(NA * AFD + 255) / 256, 256>>>(atom_num, emb);
    nbrcvt_k<<<(NA * MM * NFP + 255) / 256, 256>>>(nbr_fea);

    for (int i = 0; i < NCONV; i++) {
        const float* Wlp = W_full + (size_t)i * KD * CD;
        const float* blp = b_full + (size_t)i * CD;
        selfg_k<<<(NA + 127) / 128, 512, SG_DYN>>>(Wlp, blp);
        convg<<<NBLK2, 256, SMEM_DYN>>>(nidx, Wlp);
        fin1_k<<<1, 512>>>(bn1g + (size_t)i * CD, bn1b + (size_t)i * CD);
        pass2s_k<<<G2BLK, 256>>>();
        fin2_k<<<1, 512>>>(bn2g + (size_t)i * AFD, bn2b + (size_t)i * AFD);
        update_k<<<(NA * AFD + 255) / 256, 256>>>(fin, fout);
        float* tmp = fin; fin = fout; fout = tmp;
    }

    head_k<<<NCRY, 128>>>(fin, cai, Wfc, bfc, Wout, bout, out);
}

// round 16
// speedup vs baseline: 2.0669x; 1.0383x over previous
#include <cuda_runtime.h>
#include <cuda_fp16.h>
#include <cstdint>

#define NA   100000
#define MM   12
#define AFD  64
#define NFD  41
#define KD   169
#define CD   128
#define NCONV 3
#define NCRY 100
#define APC  1000
#define HF   128
#define HID  64
#define EPSV 1e-5f

#define NBLK2  296             // convg grid (2 CTAs/SM)
#define TATOMS 5
#define NTILES (NA / TATOMS)   // 20000
#define TROWS  60
#define KSTEPS 7               // K_rest = 112 (64 nbr + 48 bond-pad)
#define ASTRE  120
#define ASTRB  240
#define NFP    48

#define G2BLK  1184

// ---- convg SMEM byte offsets (from 1024-aligned base) ----
#define W_OFF     0u           // 128 ch x 120 k x 2B (k 105..119 zero)
#define GA_OFF    30720u       // 2 stages x STG_B
#define STG_B     16000u       // A 14400 | self 1360 | pad
#define SELF_IN   14400u
#define SIDX_OFF  62720u       // 2 x 64 i32
#define SMEM_USED 63232u
#define SMEM_DYN  (SMEM_USED + 1024u)
// stat-reduction overlay (after mainloop)
#define SREDS_OFF GA_OFF
#define SREDQ_OFF (GA_OFF + 8704u)

// ---- selfg SMEM ----
#define SGA_OFF 0u             // 128 rows x 144B
#define SGW_OFF 18432u         // 128 ch x 144B
#define SGBIAS  36864u
#define SG_USED 37376u
#define SG_DYN  (SG_USED + 1024u)

typedef unsigned long long ull;

// ---------------- scratch (device globals) ----------------------------------
__device__ float g_fea0[NA * AFD];
__device__ float g_fea1[NA * AFD];
__device__ float g_summed[NA * AFD];
__device__ __half g_gated[NA * MM * CD];         // 307 MB fp16
__device__ __half g_self[NA * CD];               // 25.6 MB fp16
__device__ __half g_AF[NA * AFD];                // fp16 atom features
__device__ __half g_NF[NA * MM * NFP];           // fp16 bond features (padded)
__device__ float g_part1[NBLK2 * 2 * CD];
__device__ float g_part2[G2BLK * 2 * AFD];
__device__ float g_sc1[CD], g_sh1[CD];
__device__ float g_sc2[AFD], g_sh2[AFD];

// ---------------- helpers ----------------------------------------------------
__device__ __forceinline__ uint32_t smem_u32(const void* p) {
    uint32_t a;
    asm("{ .reg .u64 t; cvta.to.shared.u64 t, %1; cvt.u32.u64 %0, t; }"
        : "=r"(a) : "l"(p));
    return a;
}

#define LDSM4(r, addr) \
    asm volatile("ldmatrix.sync.aligned.m8n8.x4.shared.b16 {%0,%1,%2,%3},[%4];" \
        : "=r"((r)[0]), "=r"((r)[1]), "=r"((r)[2]), "=r"((r)[3]) : "r"(addr))

#define MMAH(c, a, b) \
    asm volatile("mma.sync.aligned.m16n8k16.row.col.f32.f16.f16.f32 " \
        "{%0,%1,%2,%3},{%4,%5,%6,%7},{%8,%9},{%0,%1,%2,%3};" \
        : "+f"((c)[0]), "+f"((c)[1]), "+f"((c)[2]), "+f"((c)[3]) \
        : "r"((a)[0]), "r"((a)[1]), "r"((a)[2]), "r"((a)[3]), \
          "r"((b)[0]), "r"((b)[1]))

#define CPA16(dst, src) \
    asm volatile("cp.async.cg.shared.global [%0],[%1],16;" \
        :: "r"(dst), "l"(src) : "memory")
#define CPA_COMMIT() asm volatile("cp.async.commit_group;" ::: "memory")
#define CPA_WAIT1()  asm volatile("cp.async.wait_group 1;" ::: "memory")

__device__ __forceinline__ float sigm(float x) {
    return __fdividef(1.0f, 1.0f + __expf(-x));
}
__device__ __forceinline__ float sftp(float x) {
    return fmaxf(x, 0.0f) + __logf(1.0f + __expf(-fabsf(x)));
}

// ---------------- embedding + bond preconversion -----------------------------
__global__ void embed2_k(const int* __restrict__ an, const float* __restrict__ emb) {
    int i = blockIdx.x * blockDim.x + threadIdx.x;
    if (i < NA * AFD) {
        int n = i >> 6, c = i & 63;
        float v = emb[an[n] * AFD + c];
        g_fea0[i] = v;
        g_AF[i] = __float2half(v);
    }
}
__global__ void nbrcvt_k(const float* __restrict__ nbrf) {
    int i = blockIdx.x * blockDim.x + threadIdx.x;
    if (i < NA * MM * NFP) {
        int r = i / NFP, k = i - r * NFP;
        float v = (k < NFD) ? nbrf[r * NFD + k] : 0.0f;
        g_NF[i] = __float2half(v);
    }
}

// ---------------- selfg: S = atom_fea @ W[0:64] + bias -> fp16 ---------------
__global__ void __launch_bounds__(512, 1) selfg_k(
    const float* __restrict__ Wl, const float* __restrict__ bl)
{
    extern __shared__ char smraw[];
    char* base = (char*)((((uintptr_t)smraw) + 1023) & ~(uintptr_t)1023);
    const uint32_t bu = smem_u32(base);

    const int tid = threadIdx.x, wid = tid >> 5, lane = tid & 31;
    const int warp_m = wid & 3, warp_n = wid >> 2;
    const int R0 = warp_m * 32, N0 = warp_n * 32;
    const int n0 = blockIdx.x * 128;

    for (int i = tid; i < 128 * 8; i += 512) {
        int r = i >> 3, c = i & 7;
        uint4 v = make_uint4(0, 0, 0, 0);
        if (n0 + r < NA)
            v = *(const uint4*)((const char*)g_AF + (size_t)(n0 + r) * 128 + c * 16);
        *(uint4*)(base + SGA_OFF + r * 144 + c * 16) = v;
    }
    for (int i = tid; i < 64 * 128; i += 512) {
        int k = i >> 7, c = i & 127;
        *(__half*)(base + SGW_OFF + c * 144 + k * 2) = __float2half(Wl[k * CD + c]);
    }
    if (tid < 128) ((float*)(base + SGBIAS))[tid] = bl[tid];
    __syncthreads();

    const uint32_t aoffb = (uint32_t)(((R0 + (lane & 15)) * 72 + (lane >> 4) * 8) * 2);
    const uint32_t aT0 = bu + SGA_OFF + aoffb, aT1 = aT0 + 16 * 144;
    const uint32_t boffb = (uint32_t)(((N0 + (lane & 7) + (lane >> 4) * 8) * 72
                                      + ((lane >> 3) & 1) * 8) * 2);
    const uint32_t bA = bu + SGW_OFF + boffb, bB = bA + 16 * 144;

    float bch[8];
#pragma unroll
    for (int j = 0; j < 4; j++) {
        bch[j * 2]     = ((float*)(base + SGBIAS))[N0 + j * 8 + (lane & 3) * 2];
        bch[j * 2 + 1] = ((float*)(base + SGBIAS))[N0 + j * 8 + (lane & 3) * 2 + 1];
    }

    float C[2][4][4];
#pragma unroll
    for (int mi = 0; mi < 2; mi++)
#pragma unroll
        for (int j = 0; j < 4; j++)
#pragma unroll
            for (int p = 0; p < 4; p++) C[mi][j][p] = 0.0f;

#pragma unroll
    for (int ks = 0; ks < 4; ks++) {
        const uint32_t ko = (uint32_t)ks * 32u;
        uint32_t a0[4], a1[4], wA[4], wB[4];
        LDSM4(a0, aT0 + ko); LDSM4(a1, aT1 + ko);
        LDSM4(wA, bA + ko);  LDSM4(wB, bB + ko);
        MMAH(C[0][0], a0, wA + 0); MMAH(C[0][1], a0, wA + 2);
        MMAH(C[0][2], a0, wB + 0); MMAH(C[0][3], a0, wB + 2);
        MMAH(C[1][0], a1, wA + 0); MMAH(C[1][1], a1, wA + 2);
        MMAH(C[1][2], a1, wB + 0); MMAH(C[1][3], a1, wB + 2);
    }

#pragma unroll
    for (int mi = 0; mi < 2; mi++) {
        int r0 = R0 + mi * 16 + (lane >> 2);
        int r1 = r0 + 8;
#pragma unroll
        for (int j = 0; j < 4; j++) {
            int col = N0 + j * 8 + (lane & 3) * 2;
            if (n0 + r0 < NA)
                *(__half2*)&g_self[(size_t)(n0 + r0) * CD + col] =
                    __floats2half2_rn(C[mi][j][0] + bch[j * 2],
                                      C[mi][j][1] + bch[j * 2 + 1]);
            if (n0 + r1 < NA)
                *(__half2*)&g_self[(size_t)(n0 + r1) * CD + col] =
                    __floats2half2_rn(C[mi][j][2] + bch[j * 2],
                                      C[mi][j][3] + bch[j * 2 + 1]);
        }
    }
}

// ---------------- convg: fp16 rest-GEMM, W fragments register-resident -------
// 256 threads, 2 CTAs/SM. Tile 60 rows (5 atoms) x 128 ch, double-buffered.
__global__ void __launch_bounds__(256, 2) convg(const int* __restrict__ nidx,
                                                const float* __restrict__ Wl)
{
    extern __shared__ char smraw[];
    char* base = (char*)((((uintptr_t)smraw) + 1023) & ~(uintptr_t)1023);
    const uint32_t bu = smem_u32(base);

    const int tid = threadIdx.x, wid = tid >> 5, lane = tid & 31;
    const int warp_m = wid & 1, warp_n = wid >> 1;
    const int R0 = warp_m * 32, N0 = warp_n * 32;
    int* sIdx = (int*)(base + SIDX_OFF);

    for (int i = tid; i < (int)(SMEM_USED / 4); i += 256) ((uint32_t*)base)[i] = 0;
    __syncthreads();

    // W^T fp16 for k_global 64..168 (local 0..104; 105..119 stay zero)
    for (int i = tid; i < 105 * 128; i += 256) {
        int k = i >> 7, c = i & 127;
        *(__half*)(base + W_OFF + c * ASTRB + k * 2) = __float2half(Wl[(64 + k) * CD + c]);
    }

    int tile = blockIdx.x;
    if (tid < TROWS) sIdx[tid] = nidx[tile * TROWS + tid];
    __syncthreads();

    // hoist W fragments: tile-invariant, 56 registers, loaded ONCE
    const uint32_t boffb = (uint32_t)(((N0 + (lane & 7) + (lane >> 4) * 8) * ASTRE
                                      + ((lane >> 3) & 1) * 8) * 2);
    const uint32_t bA = bu + W_OFF + boffb, bB = bA + 16 * ASTRB;
    uint32_t wrA[KSTEPS][4], wrB[KSTEPS][4];
#pragma unroll
    for (int ks = 0; ks < KSTEPS; ks++) {
        LDSM4(wrA[ks], bA + (uint32_t)ks * 32u);
        LDSM4(wrB[ks], bB + (uint32_t)ks * 32u);
    }

    // staging: A fp16 (nbr 128B + bond 96B per row) + self fp16 (256B/atom)
    auto STAGE = [&](int t, int sbuf) {
        const int rbase = t * TROWS;
        const int a0 = t * TATOMS;
        const int* sx = sIdx + sbuf * 64;
        const uint32_t dA = bu + GA_OFF + (uint32_t)sbuf * STG_B;
        const uint32_t dS = dA + SELF_IN;
        for (int i = tid; i < TROWS * 14 + 80; i += 256) {
            if (i < TROWS * 14) {
                int r = i / 14, c = i - r * 14;
                const char* src;
                uint32_t doff;
                if (c < 8) {
                    src = (const char*)g_AF + (size_t)sx[r] * 128 + c * 16;
                    doff = (uint32_t)(r * ASTRB + c * 16);
                } else {
                    src = (const char*)g_NF + (size_t)(rbase + r) * 96 + (c - 8) * 16;
                    doff = (uint32_t)(r * ASTRB + 128 + (c - 8) * 16);
                }
                CPA16(dA + doff, src);
            } else {
                int i2 = i - TROWS * 14;
                int a = i2 >> 4, c = i2 & 15;    // 5 atoms x 16 x 16B
                CPA16(dS + (uint32_t)(a * 272 + c * 16),
                      (const char*)g_self + (size_t)(a0 + a) * 256 + c * 16);
            }
        }
    };

    STAGE(tile, 0);
    CPA_COMMIT();
    int idxNext = 0;
    if (tile + NBLK2 < NTILES && tid < TROWS)
        idxNext = nidx[(tile + NBLK2) * TROWS + tid];

    const uint32_t aoffb = (uint32_t)(((R0 + (lane & 15)) * ASTRE + (lane >> 4) * 8) * 2);

    float sS[8], sQ[8];
#pragma unroll
    for (int j = 0; j < 8; j++) { sS[j] = 0.0f; sQ[j] = 0.0f; }

    for (int it = 0; tile < NTILES; it++, tile += NBLK2) {
        const int nxt = tile + NBLK2;
        const int sb = it & 1;

        if (nxt < NTILES && tid < TROWS)
            sIdx[(sb ^ 1) * 64 + tid] = idxNext;
        __syncthreads();               // prev GEMM done with buf sb^1; sIdx visible
        if (nxt < NTILES) STAGE(nxt, sb ^ 1);
        CPA_COMMIT();
        if (nxt + NBLK2 < NTILES && tid < TROWS)
            idxNext = nidx[(nxt + NBLK2) * TROWS + tid];
        CPA_WAIT1();
        __syncthreads();

        const uint32_t dA = bu + GA_OFF + (uint32_t)sb * STG_B;
        const uint32_t aT0 = dA + aoffb, aT1 = aT0 + 16 * ASTRB;
        const char* selfB = base + GA_OFF + (size_t)sb * STG_B + SELF_IN;

        float C[2][4][4];
#pragma unroll
        for (int mi = 0; mi < 2; mi++)
#pragma unroll
            for (int j = 0; j < 4; j++)
#pragma unroll
                for (int p = 0; p < 4; p++) C[mi][j][p] = 0.0f;

#pragma unroll
        for (int ks = 0; ks < KSTEPS; ks++) {
            const uint32_t ko = (uint32_t)ks * 32u;
            uint32_t a0[4], a1[4];
            LDSM4(a0, aT0 + ko); LDSM4(a1, aT1 + ko);
            MMAH(C[0][0], a0, wrA[ks] + 0); MMAH(C[0][1], a0, wrA[ks] + 2);
            MMAH(C[0][2], a0, wrB[ks] + 0); MMAH(C[0][3], a0, wrB[ks] + 2);
            MMAH(C[1][0], a1, wrA[ks] + 0); MMAH(C[1][1], a1, wrA[ks] + 2);
            MMAH(C[1][2], a1, wrB[ks] + 0); MMAH(C[1][3], a1, wrB[ks] + 2);
        }

        // ---- epilogue: + self (fp16 SMEM), store gated fp16, stats ----
        const int growb = tile * TROWS;
#pragma unroll
        for (int mi = 0; mi < 2; mi++) {
            const int r0 = R0 + mi * 16 + (lane >> 2);
            const int r1 = r0 + 8;
            const bool v1 = (r1 < TROWS);     // rows 60..63 are pad
            const int a0l = r0 / MM;
            const int a1l = v1 ? (r1 / MM) : 0;
#pragma unroll
            for (int j = 0; j < 4; j++) {
                const int col = N0 + j * 8 + (lane & 3) * 2;
                float2 s0 = __half22float2(
                    *(const __half2*)(selfB + a0l * 272 + col * 2));
                float g0 = C[mi][j][0] + s0.x;
                float g1 = C[mi][j][1] + s0.y;
                *(__half2*)&g_gated[(size_t)(growb + r0) * CD + col] =
                    __floats2half2_rn(g0, g1);
                sS[j * 2] += g0; sS[j * 2 + 1] += g1;
                sQ[j * 2] = fmaf(g0, g0, sQ[j * 2]);
                sQ[j * 2 + 1] = fmaf(g1, g1, sQ[j * 2 + 1]);
                if (v1) {
                    float2 s1 = __half22float2(
                        *(const __half2*)(selfB + a1l * 272 + col * 2));
                    float g2 = C[mi][j][2] + s1.x;
                    float g3 = C[mi][j][3] + s1.y;
                    *(__half2*)&g_gated[(size_t)(growb + r1) * CD + col] =
                        __floats2half2_rn(g2, g3);
                    sS[j * 2] += g2; sS[j * 2 + 1] += g3;
                    sQ[j * 2] = fmaf(g2, g2, sQ[j * 2]);
                    sQ[j * 2 + 1] = fmaf(g3, g3, sQ[j * 2 + 1]);
                }
            }
        }
    }

    // ---- deterministic per-block stat reduction (overlay stages) ----
    __syncthreads();
    {
        float* sredS = (float*)(base + SREDS_OFF);   // [128][17]
        float* sredQ = (float*)(base + SREDQ_OFF);
        const int idx = warp_m * 8 + (lane >> 2);    // 0..15
#pragma unroll
        for (int j = 0; j < 4; j++)
#pragma unroll
            for (int e = 0; e < 2; e++) {
                int c = N0 + j * 8 + (lane & 3) * 2 + e;
                sredS[c * 17 + idx] = sS[j * 2 + e];
                sredQ[c * 17 + idx] = sQ[j * 2 + e];
            }
        __syncthreads();
        int stat = tid >> 7, c = tid & 127;
        const float* p = stat ? sredQ : sredS;
        float v = 0.0f;
#pragma unroll
        for (int w = 0; w < 16; w++) v += p[c * 17 + w];
        g_part1[blockIdx.x * 2 * CD + tid] = v;
    }
}

// ---------------- streaming pass2 (half2, 2 channels/thread) -----------------
__global__ void __launch_bounds__(256) pass2s_k() {
    const int tid = threadIdx.x;
    const int w0 = blockIdx.x * 256 + tid;
    const int cp = w0 & 31;                        // invariant across grid stride
    const int c = cp * 2;
    const float scF0 = g_sc1[c],      shF0 = g_sh1[c];
    const float scF1 = g_sc1[c + 1],  shF1 = g_sh1[c + 1];
    const float scC0 = g_sc1[64 + c], shC0 = g_sh1[64 + c];
    const float scC1 = g_sc1[65 + c], shC1 = g_sh1[65 + c];

    float ss0 = 0, ss1 = 0, sq0 = 0, sq1 = 0;
    for (int o = w0; o < NA * 32; o += G2BLK * 256) {
        const int n = o >> 5;
        const __half* gp = g_gated + (size_t)n * (MM * CD);
        float s0 = 0.0f, s1 = 0.0f;
#pragma unroll
        for (int m = 0; m < MM; m++) {
            float2 f2 = __half22float2(*(const __half2*)&gp[m * CD + c]);
            float2 c2 = __half22float2(*(const __half2*)&gp[m * CD + 64 + c]);
            float f0 = fmaf(f2.x, scF0, shF0), f1 = fmaf(f2.y, scF1, shF1);
            float o0 = fmaf(c2.x, scC0, shC0), o1 = fmaf(c2.y, scC1, shC1);
            s0 += sigm(f0) * sftp(o0);
            s1 += sigm(f1) * sftp(o1);
        }
        *(float2*)&g_summed[(size_t)n * AFD + c] = make_float2(s0, s1);
        ss0 += s0; ss1 += s1;
        sq0 = fmaf(s0, s0, sq0); sq1 = fmaf(s1, s1, sq1);
    }

    __shared__ float sr[4][256];
    sr[0][tid] = ss0; sr[1][tid] = ss1; sr[2][tid] = sq0; sr[3][tid] = sq1;
    __syncthreads();
    if (tid < 128) {
        int st = tid >> 6, ch = tid & 63;
        int cpair = ch >> 1, e = ch & 1;
        const float* p = sr[st * 2 + e];
        float v = 0.0f;
#pragma unroll
        for (int q = 0; q < 8; q++) v += p[q * 32 + cpair];
        g_part2[blockIdx.x * 128 + tid] = v;
    }
}

// ---------------- BN finalize ------------------------------------------------
__global__ void __launch_bounds__(512) fin1_k(const float* __restrict__ g,
                                              const float* __restrict__ b) {
    __shared__ float sm[2][512];
    int tid = threadIdx.x, c = tid & 127, grp = tid >> 7;
    float s = 0, q = 0;
    for (int bl = grp; bl < NBLK2; bl += 4) {
        s += g_part1[bl * 2 * CD + c];
        q += g_part1[bl * 2 * CD + CD + c];
    }
    sm[0][tid] = s; sm[1][tid] = q;
    __syncthreads();
    if (tid < 128) {
        float S = sm[0][tid] + sm[0][128 + tid] + sm[0][256 + tid] + sm[0][384 + tid];
        float Q = sm[1][tid] + sm[1][128 + tid] + sm[1][256 + tid] + sm[1][384 + tid];
        const float inv = 1.0f / ((float)NA * (float)MM);
        float mu = S * inv;
        float var = Q * inv - mu * mu;
        float sc = g[tid] * rsqrtf(var + EPSV);
        g_sc1[tid] = sc;
        g_sh1[tid] = b[tid] - mu * sc;
    }
}
__global__ void __launch_bounds__(512) fin2_k(const float* __restrict__ g,
                                              const float* __restrict__ b) {
    __shared__ float sm[2][512];
    int tid = threadIdx.x, c = tid & 63, grp = tid >> 6;
    float s = 0, q = 0;
    for (int bl = grp; bl < G2BLK; bl += 8) {
        s += g_part2[bl * 128 + c];
        q += g_part2[bl * 128 + 64 + c];
    }
    sm[0][tid] = s; sm[1][tid] = q;
    __syncthreads();
    if (tid < 64) {
        float S = 0, Q = 0;
#pragma unroll
        for (int w = 0; w < 8; w++) { S += sm[0][w * 64 + tid]; Q += sm[1][w * 64 + tid]; }
        const float inv = 1.0f / (float)NA;
        float mu = S * inv;
        float var = Q * inv - mu * mu;
        float sc = g[tid] * rsqrtf(var + EPSV);
        g_sc2[tid] = sc;
        g_sh2[tid] = b[tid] - mu * sc;
    }
}

// ---------------- residual + bn2 + softplus (+ fp16 features) ----------------
__global__ void update_k(const float* __restrict__ fin, float* __restrict__ fout) {
    int i = blockIdx.x * blockDim.x + threadIdx.x;
    if (i < NA * AFD) {
        int c = i & 63;
        float v = sftp(fin[i] + fmaf(g_summed[i], g_sc2[c], g_sh2[c]));
        fout[i] = v;
        g_AF[i] = __float2half(v);
    }
}

// ---------------- head -------------------------------------------------------
__global__ void head_k(const float* __restrict__ afea, const int* __restrict__ cai,
                       const float* __restrict__ Wfc, const float* __restrict__ bfc,
                       const float* __restrict__ Wout, const float* __restrict__ bout,
                       float* __restrict__ out) {
    __shared__ float scry[AFD];
    __shared__ float shid[HF];
    __shared__ float part[2][AFD];
    int b = blockIdx.x, t = threadIdx.x;
    int c = t & 63, h = t >> 6;

    const int* idx = cai + b * APC;
    float acc = 0;
    for (int a = h * (APC / 2); a < (h + 1) * (APC / 2); a++)
        acc += afea[idx[a] * AFD + c];
    part[h][c] = acc;
    __syncthreads();

    if (t < AFD) scry[t] = sftp((part[0][t] + part[1][t]) * (1.0f / (float)APC));
    __syncthreads();

    float a2 = bfc[t];
    for (int k = 0; k < AFD; k++) a2 = fmaf(scry[k], Wfc[k * HF + t], a2);
    shid[t] = sftp(a2);
    __syncthreads();

    if (t < HID) {
        float a3 = bout[t];
        for (int k = 0; k < HF; k++) a3 = fmaf(shid[k], Wout[k * HID + t], a3);
        out[b * HID + t] = a3;
    }
}

// ---------------- launch -----------------------------------------------------
extern "C" void kernel_launch(void* const* d_in, const int* in_sizes, int n_in,
                              void* d_out, int out_size) {
    const int*   atom_num = (const int*)d_in[0];
    const float* nbr_fea  = (const float*)d_in[1];
    const int*   nidx     = (const int*)d_in[2];
    const int*   cai      = (const int*)d_in[3];
    const float* emb      = (const float*)d_in[4];
    const float* W_full   = (const float*)d_in[5];
    const float* b_full   = (const float*)d_in[6];
    const float* bn1g     = (const float*)d_in[7];
    const float* bn1b     = (const float*)d_in[8];
    const float* bn2g     = (const float*)d_in[9];
    const float* bn2b     = (const float*)d_in[10];
    const float* Wfc      = (const float*)d_in[11];
    const float* bfc      = (const float*)d_in[12];
    const float* Wout     = (const float*)d_in[13];
    const float* bout     = (const float*)d_in[14];
    float* out = (float*)d_out;

    cudaFuncSetAttribute(convg,   cudaFuncAttributeMaxDynamicSharedMemorySize, SMEM_DYN);
    cudaFuncSetAttribute(selfg_k, cudaFuncAttributeMaxDynamicSharedMemorySize, SG_DYN);

    void *p0, *p1;
    cudaGetSymbolAddress(&p0, g_fea0);
    cudaGetSymbolAddress(&p1, g_fea1);
    float* fin  = (float*)p0;
    float* fout = (float*)p1;

    embed2_k<<<(NA * AFD + 255) / 256, 256>>>(atom_num, emb);
    nbrcvt_k<<<(NA * MM * NFP + 255) / 256, 256>>>(nbr_fea);

    for (int i = 0; i < NCONV; i++) {
        const float* Wlp = W_full + (size_t)i * KD * CD;
        const float* blp = b_full + (size_t)i * CD;
        selfg_k<<<(NA + 127) / 128, 512, SG_DYN>>>(Wlp, blp);
        convg<<<NBLK2, 256, SMEM_DYN>>>(nidx, Wlp);
        fin1_k<<<1, 512>>>(bn1g + (size_t)i * CD, bn1b + (size_t)i * CD);
        pass2s_k<<<G2BLK, 256>>>();
        fin2_k<<<1, 512>>>(bn2g + (size_t)i * AFD, bn2b + (size_t)i * AFD);
        update_k<<<(NA * AFD + 255) / 256, 256>>>(fin, fout);
        float* tmp = fin; fin = fout; fout = tmp;
    }

    head_k<<<NCRY, 128>>>(fin, cai, Wfc, bfc, Wout, bout, out);
}